// round 7
// baseline (speedup 1.0000x reference)
#include <cuda_runtime.h>
#include <cstddef>

// ManyBodyVoxel: out[0, a, c=t*2+l, x, y, z] =
//   sum_n exp(coeff * || grid_l[x,y,z] - d[a,n]*mask_t[a,n] ||^2)
// Separable Gaussian -> rank-1 outer products of per-(atom,axis) exp rows.
// R7: classified-contiguous records (R6) + atom-parity lane split: each thread
//     accumulates the FULL z-column for every 2nd atom (fat iterations, fewer
//     LDS wavefronts), lane pairs combine via shfl_xor and store z-halves.

#define NT 1024

typedef unsigned long long u64;

__device__ __forceinline__ u64 pk2(float v) {
    u64 r; asm("mov.b64 %0, {%1, %2};" : "=l"(r) : "f"(v), "f"(v)); return r;
}
__device__ __forceinline__ u64 fma2(u64 a, u64 b, u64 c) {
    u64 d; asm("fma.rn.f32x2 %0, %1, %2, %3;" : "=l"(d) : "l"(a), "l"(b), "l"(c)); return d;
}
__device__ __forceinline__ u64 mul2(u64 a, u64 b) {
    u64 d; asm("mul.rn.f32x2 %0, %1, %2;" : "=l"(d) : "l"(a), "l"(b)); return d;
}
__device__ __forceinline__ u64 add2(u64 a, u64 b) {
    u64 d; asm("add.rn.f32x2 %0, %1, %2;" : "=l"(d) : "l"(a), "l"(b)); return d;
}

__global__ __launch_bounds__(NT, 1)
void mbv_kernel(const float* __restrict__ dist,   // (1,128,64,3) fp32
                const float* __restrict__ sigma,  // (1,) fp32
                const int*   __restrict__ anum,   // (128,64) int64 or int32 (auto-detect)
                float* __restrict__ out)          // (1,128,10,16,16,16) fp32
{
    const int a   = blockIdx.x;
    const int tid = threadIdx.x;
    const int pp  = tid & 1;          // atom parity this lane handles
    const int y   = (tid >> 1) & 15;
    const int x   = (tid >> 5) & 15;
    const int l   = tid >> 9;         // 0: L=8, 1: L=12

    // Record (l, slot): 64 floats = 256B. x @ +0, y @ +64B, z @ +128B, pad.
    // Slots 0..ncls-1: classified atoms (type-major compact); slot 64: base (d=0).
    __shared__ __align__(16) float tab[2 * 65 * 64];
    __shared__ float dsm[192];
    __shared__ short ord[64];
    __shared__ int   startc[5];
    __shared__ int   cntc[5];
    __shared__ int   nclss;

    const float s  = sigma[0];
    const float cf = -0.5f / (s * s);

    // ---- Phase 0: warp0 classifies (ballot compaction); threads 64..255 stage dist ----
    if (tid < 32) {
        int4 p = ((const int4*)anum)[tid];            // probe row 0 (dtype)
        int4 q = ((const int4*)anum)[a * 32 + tid];   // int64 view
        int2 r = ((const int2*)anum)[a * 32 + tid];   // int32 view
        bool i32 = __any_sync(0xffffffffu, (p.y | p.w) != 0);
        int z0 = i32 ? r.x : q.x;
        int z1 = i32 ? r.y : q.z;
        unsigned lt = (1u << tid) - 1u;
        const int ZT[5] = {1, 6, 7, 8, 16};
        int base = 0;
        #pragma unroll
        for (int t = 0; t < 5; t++) {
            unsigned m0 = __ballot_sync(0xffffffffu, z0 == ZT[t]);
            unsigned m1 = __ballot_sync(0xffffffffu, z1 == ZT[t]);
            int c0 = __popc(m0), c = c0 + __popc(m1);
            if (z0 == ZT[t]) ord[base + __popc(m0 & lt)]      = (short)(2 * tid);
            if (z1 == ZT[t]) ord[base + c0 + __popc(m1 & lt)] = (short)(2 * tid + 1);
            if (tid == 0) { startc[t] = base; cntc[t] = c; }
            base += c;
        }
        if (tid == 0) nclss = base;
    } else if (tid < 256) {
        dsm[tid - 64] = dist[a * 192 + (tid - 64)];
    }

    __syncthreads();

    // ---- Phase 1: exp tables in classified order ----
    {
        const int nrec = nclss + 1;
        const int lp = tid & 1;
        const int u  = tid >> 1;
        if (u < 6 * nrec) {
            int slot = u / 6;
            int rem  = u - slot * 6;
            int ax   = rem >> 1;
            int jh   = rem & 1;
            int isbase = (slot == nclss);
            int recid  = isbase ? 64 : slot;
            float dv   = isbase ? 0.0f : dsm[ord[slot] * 3 + ax];
            float Lp   = lp ? 12.0f : 8.0f;
            float half = 0.5f * Lp;
            float step = Lp * (1.0f / 15.0f);
            float* dst = &tab[(lp * 65 + recid) * 64 + ax * 16 + jh * 8];
            float bse  = -half - dv + step * (float)(jh * 8);
            #pragma unroll
            for (int j = 0; j < 8; j++) {
                float uu = bse + step * (float)j;
                dst[j] = __expf(cf * uu * uu);
            }
        }
    }

    __syncthreads();

    // ---- Phase 2: consumer. Lane pair (pp=0/1) splits atoms; full z per thread ----
    const char* tb = reinterpret_cast<const char*>(tab) + l * (65 * 256);
    const int offx = x * 4;
    const int offy = 64 + y * 4;

    const char* br = tb + 64 * 256;   // base record
    const float bxy = *(const float*)(br + offx) * *(const float*)(br + offy);
    const ulonglong2* bz = reinterpret_cast<const ulonglong2*>(br + 128);
    const ulonglong2 bza = bz[0], bzb = bz[1], bzc = bz[2], bzd = bz[3];

    // store: channel = a*10 + t*2 + l; this lane stores z in [pp*8, pp*8+8)
    char* op = reinterpret_cast<char*>(out)
             + ((((size_t)(a * 10 + l)) << 12) + ((size_t)x << 8) + ((size_t)y << 4) + ((size_t)pp << 3)) * 4;

    #pragma unroll
    for (int t = 0; t < 5; t++) {
        const int c  = cntc[t];
        const int st = startc[t];
        // parity 0 carries the base term; parity 1 starts at zero
        const u64 bm = pk2(pp ? 0.0f : (float)(64 - c) * bxy);
        u64 a0 = mul2(bm, bza.x), a1 = mul2(bm, bza.y);
        u64 a2 = mul2(bm, bzb.x), a3 = mul2(bm, bzb.y);
        u64 a4 = mul2(bm, bzc.x), a5 = mul2(bm, bzc.y);
        u64 a6 = mul2(bm, bzd.x), a7 = mul2(bm, bzd.y);

        const char* p = tb + (st + pp) * 256;
        for (int k = pp; k < c; k += 2) {
            float sx = *(const float*)(p + offx);
            float sy = *(const float*)(p + offy);
            const ulonglong2* zp = reinterpret_cast<const ulonglong2*>(p + 128);
            ulonglong2 q0 = zp[0], q1 = zp[1], q2 = zp[2], q3 = zp[3];
            u64 sp = pk2(sx * sy);
            a0 = fma2(sp, q0.x, a0); a1 = fma2(sp, q0.y, a1);
            a2 = fma2(sp, q1.x, a2); a3 = fma2(sp, q1.y, a3);
            a4 = fma2(sp, q2.x, a4); a5 = fma2(sp, q2.y, a5);
            a6 = fma2(sp, q3.x, a6); a7 = fma2(sp, q3.y, a7);
            p += 512;
        }

        // Combine lane pairs: this lane finalizes its z-half [pp*8, pp*8+8).
        u64 h0 = pp ? a4 : a0, h1 = pp ? a5 : a1;
        u64 h2 = pp ? a6 : a2, h3 = pp ? a7 : a3;
        u64 o0 = pp ? a0 : a4, o1 = pp ? a1 : a5;
        u64 o2 = pp ? a2 : a6, o3 = pp ? a3 : a7;
        // partner holds the other partial of MY half in its corresponding regs
        h0 = add2(h0, __shfl_xor_sync(0xffffffffu, o0, 1));
        h1 = add2(h1, __shfl_xor_sync(0xffffffffu, o1, 1));
        h2 = add2(h2, __shfl_xor_sync(0xffffffffu, o2, 1));
        h3 = add2(h3, __shfl_xor_sync(0xffffffffu, o3, 1));

        __stcs((ulonglong2*)op,        make_ulonglong2(h0, h1));
        __stcs((ulonglong2*)(op + 16), make_ulonglong2(h2, h3));
        op += 2 * 4096 * 4;   // next type channel
    }
}

extern "C" void kernel_launch(void* const* d_in, const int* in_sizes, int n_in,
                              void* d_out, int out_size) {
    const float* dist = nullptr;
    const float* sig  = nullptr;
    const int*   an   = nullptr;
    for (int i = 0; i < n_in; i++) {
        if (in_sizes[i] == 1)          sig  = (const float*)d_in[i];
        else if (in_sizes[i] == 24576) dist = (const float*)d_in[i];
        else if (in_sizes[i] == 8192)  an   = (const int*)d_in[i];
    }
    if (!dist) dist = (const float*)d_in[0];
    if (!sig)  sig  = (const float*)d_in[1];
    if (!an)   an   = (const int*)d_in[2];

    mbv_kernel<<<128, NT>>>(dist, sig, an, (float*)d_out);
}

// round 8
// speedup vs baseline: 1.1805x; 1.1805x over previous
#include <cuda_runtime.h>
#include <cstddef>

// ManyBodyVoxel: out[0, a, c=t*2+l, x, y, z] =
//   sum_n exp(coeff * || grid_l[x,y,z] - d[a,n]*mask_t[a,n] ||^2)
// Separable Gaussian -> rank-1 outer products of per-(atom,axis) exp rows.
// R8: grid=256 (one CTA per (a,l)) x 1024 threads, 2 CTAs/SM (64 warps = occ 100%),
//     thread = (x, y, z-quarter), <=32 regs, classified-contiguous records,
//     branchless 7-instr inner loop.

#define NT 1024

typedef unsigned long long u64;

__device__ __forceinline__ u64 pk2(float v) {
    u64 r; asm("mov.b64 %0, {%1, %2};" : "=l"(r) : "f"(v), "f"(v)); return r;
}
__device__ __forceinline__ u64 fma2(u64 a, u64 b, u64 c) {
    u64 d; asm("fma.rn.f32x2 %0, %1, %2, %3;" : "=l"(d) : "l"(a), "l"(b), "l"(c)); return d;
}
__device__ __forceinline__ u64 mul2(u64 a, u64 b) {
    u64 d; asm("mul.rn.f32x2 %0, %1, %2;" : "=l"(d) : "l"(a), "l"(b)); return d;
}

__global__ __launch_bounds__(NT, 2)
void mbv_kernel(const float* __restrict__ dist,   // (1,128,64,3) fp32
                const float* __restrict__ sigma,  // (1,) fp32
                const int*   __restrict__ anum,   // (128,64) int64 or int32 (auto-detect)
                float* __restrict__ out)          // (1,128,10,16,16,16) fp32
{
    const int a   = blockIdx.x >> 1;
    const int l   = blockIdx.x & 1;   // 0: L=8, 1: L=12
    const int tid = threadIdx.x;
    const int zq  = tid & 3;          // z quarter: [zq*4, zq*4+4)
    const int y   = (tid >> 2) & 15;
    const int x   = (tid >> 6) & 15;

    // Record (slot): 64 floats = 256B. x @ +0, y @ +64B, z @ +128B, pad.
    // Slots 0..ncls-1: classified atoms (type-major compact); slot 64: base (d=0).
    __shared__ __align__(16) float tab[65 * 64];
    __shared__ float dsm[192];
    __shared__ short ord[64];
    __shared__ int   startc[5];
    __shared__ int   cntc[5];
    __shared__ int   nclss;

    const float s  = sigma[0];
    const float cf = -0.5f / (s * s);

    // ---- Phase 0: warp0 classifies (ballot compaction); threads 32..223 stage dist ----
    if (tid < 32) {
        int4 p = ((const int4*)anum)[tid];            // probe row 0 (dtype)
        int4 q = ((const int4*)anum)[a * 32 + tid];   // int64 view
        int2 r = ((const int2*)anum)[a * 32 + tid];   // int32 view
        bool i32 = __any_sync(0xffffffffu, (p.y | p.w) != 0);
        int z0 = i32 ? r.x : q.x;
        int z1 = i32 ? r.y : q.z;
        unsigned lt = (1u << tid) - 1u;
        const int ZT[5] = {1, 6, 7, 8, 16};
        int base = 0;
        #pragma unroll
        for (int t = 0; t < 5; t++) {
            unsigned m0 = __ballot_sync(0xffffffffu, z0 == ZT[t]);
            unsigned m1 = __ballot_sync(0xffffffffu, z1 == ZT[t]);
            int c0 = __popc(m0), c = c0 + __popc(m1);
            if (z0 == ZT[t]) ord[base + __popc(m0 & lt)]      = (short)(2 * tid);
            if (z1 == ZT[t]) ord[base + c0 + __popc(m1 & lt)] = (short)(2 * tid + 1);
            if (tid == 0) { startc[t] = base; cntc[t] = c; }
            base += c;
        }
        if (tid == 0) nclss = base;
    } else if (tid < 224) {
        dsm[tid - 32] = dist[a * 192 + (tid - 32)];
    }

    __syncthreads();

    // ---- Phase 1: exp tables (this CTA's l only) in classified order ----
    {
        const int nrec = nclss + 1;
        if (tid < 6 * nrec) {                 // unit = (slot, ax, jhalf)
            int slot = tid / 6;
            int rem  = tid - slot * 6;
            int ax   = rem >> 1;
            int jh   = rem & 1;
            int isbase = (slot == nclss);
            int recid  = isbase ? 64 : slot;
            float dv   = isbase ? 0.0f : dsm[ord[slot] * 3 + ax];
            float Lp   = l ? 12.0f : 8.0f;
            float half = 0.5f * Lp;
            float step = Lp * (1.0f / 15.0f);
            float* dst = &tab[recid * 64 + ax * 16 + jh * 8];
            float bse  = -half - dv + step * (float)(jh * 8);
            #pragma unroll
            for (int j = 0; j < 8; j++) {
                float uu = bse + step * (float)j;
                dst[j] = __expf(cf * uu * uu);
            }
        }
    }

    __syncthreads();

    // ---- Phase 2: consumer. Thread owns 4 voxels z in [zq*4, zq*4+4) of (x,y) ----
    const char* tb = reinterpret_cast<const char*>(tab);
    const int offx = x * 4;
    const int offy = 64 + y * 4;
    const int offz = 128 + zq * 16;

    const char* br = tb + 64 * 256;   // base record
    const float bxy = *(const float*)(br + offx) * *(const float*)(br + offy);
    const ulonglong2 bq = *(const ulonglong2*)(br + offz);   // 4 base z values

    // out offset (floats): (a*10 + t*2 + l)*4096 + x*256 + y*16 + zq*4
    char* op = reinterpret_cast<char*>(out)
             + ((((size_t)(a * 10 + l)) << 12) + ((size_t)x << 8) + ((size_t)y << 4) + ((size_t)zq << 2)) * 4;

    #pragma unroll
    for (int t = 0; t < 5; t++) {
        const int c  = cntc[t];
        const u64 bm = pk2((float)(64 - c) * bxy);
        u64 a0 = mul2(bm, bq.x);
        u64 a1 = mul2(bm, bq.y);

        const char* p = tb + startc[t] * 256;
        #pragma unroll 2
        for (int k = 0; k < c; k++) {
            float sx = *(const float*)(p + offx);
            float sy = *(const float*)(p + offy);
            ulonglong2 q = *(const ulonglong2*)(p + offz);
            u64 sp = pk2(sx * sy);
            a0 = fma2(sp, q.x, a0);
            a1 = fma2(sp, q.y, a1);
            p += 256;
        }

        __stcs((ulonglong2*)op, make_ulonglong2(a0, a1));
        op += 2 * 4096 * 4;   // next type channel
    }
}

extern "C" void kernel_launch(void* const* d_in, const int* in_sizes, int n_in,
                              void* d_out, int out_size) {
    const float* dist = nullptr;
    const float* sig  = nullptr;
    const int*   an   = nullptr;
    for (int i = 0; i < n_in; i++) {
        if (in_sizes[i] == 1)          sig  = (const float*)d_in[i];
        else if (in_sizes[i] == 24576) dist = (const float*)d_in[i];
        else if (in_sizes[i] == 8192)  an   = (const int*)d_in[i];
    }
    if (!dist) dist = (const float*)d_in[0];
    if (!sig)  sig  = (const float*)d_in[1];
    if (!an)   an   = (const int*)d_in[2];

    mbv_kernel<<<256, NT>>>(dist, sig, an, (float*)d_out);
}